// round 1
// baseline (speedup 1.0000x reference)
#include <cuda_runtime.h>
#include <math.h>

#define N_NODES 50000
#define E_EDGES 800000
#define E_TOT   (E_EDGES + N_NODES)   // 850000 with self loops
#define F_IN    128
#define SLOPE   0.2f

// ---------------- scratch (static __device__ — no allocation) ----------------
__device__ float g_h[N_NODES * 128];        // transformed features (<=128 cols)
__device__ float g_o[N_NODES * 128];        // aggregated output
__device__ float g_als[N_NODES * 4];
__device__ float g_ald[N_NODES * 4];
__device__ float g_denom[N_NODES * 4];
__device__ float g_p[E_TOT * 4];

// ---------------- zero helper ----------------
__global__ void zero_kernel(float* p, int n) {
    int i = blockIdx.x * blockDim.x + threadIdx.x;
    if (i < n) p[i] = 0.f;
}

// ---------------- GEMM: H = act(X + bias) @ W ----------------
// X: [N, F_IN] fp32 row-major, W: [F_IN, MO] row-major.
// If bias != null, applies relu(x + bias[k]) to the input features (fused
// epilogue of the previous layer).
template<int MO>
__global__ void gemm_kernel(const float* __restrict__ X,
                            const float* __restrict__ W,
                            const float* __restrict__ bias,
                            float* __restrict__ Hout) {
    constexpr int ROWS = 16;
    __shared__ float4 xs[ROWS][F_IN / 4];
    const int row0 = blockIdx.x * ROWS;
    const int t = threadIdx.x;

    for (int i = t; i < ROWS * (F_IN / 4); i += MO) {
        int r  = i / (F_IN / 4);
        int k4 = i % (F_IN / 4);
        int n  = row0 + r;
        float4 v = make_float4(0.f, 0.f, 0.f, 0.f);
        if (n < N_NODES) {
            v = reinterpret_cast<const float4*>(X)[n * (F_IN / 4) + k4];
            if (bias) {
                float4 b = reinterpret_cast<const float4*>(bias)[k4];
                v.x = fmaxf(v.x + b.x, 0.f);
                v.y = fmaxf(v.y + b.y, 0.f);
                v.z = fmaxf(v.z + b.z, 0.f);
                v.w = fmaxf(v.w + b.w, 0.f);
            }
        }
        xs[r][k4] = v;
    }
    __syncthreads();

    float acc[ROWS];
#pragma unroll
    for (int r = 0; r < ROWS; r++) acc[r] = 0.f;

    for (int k4 = 0; k4 < F_IN / 4; k4++) {
        float w0 = W[(k4 * 4 + 0) * MO + t];
        float w1 = W[(k4 * 4 + 1) * MO + t];
        float w2 = W[(k4 * 4 + 2) * MO + t];
        float w3 = W[(k4 * 4 + 3) * MO + t];
#pragma unroll
        for (int r = 0; r < ROWS; r++) {
            float4 xv = xs[r][k4];
            acc[r] = fmaf(xv.x, w0, acc[r]);
            acc[r] = fmaf(xv.y, w1, acc[r]);
            acc[r] = fmaf(xv.z, w2, acc[r]);
            acc[r] = fmaf(xv.w, w3, acc[r]);
        }
    }

#pragma unroll
    for (int r = 0; r < ROWS; r++) {
        int n = row0 + r;
        if (n < N_NODES) Hout[n * MO + t] = acc[r];
    }
}

// ---------------- attention coefficients + denom zeroing ----------------
// als[n,h] = sum_f h[n,h,f]*a_src[h,f]; also zeroes denom[n,h].
template<int H, int F>
__global__ void coef_kernel(const float* __restrict__ Hfeat,
                            const float* __restrict__ a_src,
                            const float* __restrict__ a_dst,
                            float* __restrict__ als, float* __restrict__ ald,
                            float* __restrict__ denom) {
    int i = blockIdx.x * blockDim.x + threadIdx.x;   // n*H + h
    if (i >= N_NODES * H) return;
    int n = i / H, h = i % H;
    const float* hp = Hfeat + n * (H * F) + h * F;
    const float* as = a_src + h * F;
    const float* ad = a_dst + h * F;
    float s = 0.f, d = 0.f;
#pragma unroll 8
    for (int f = 0; f < F; f++) {
        float v = hp[f];
        s = fmaf(v, as[f], s);
        d = fmaf(v, ad[f], d);
    }
    als[i] = s;
    ald[i] = d;
    denom[i] = 0.f;
}

// ---------------- edge pass A: p = exp(leakyrelu(als[src]+ald[dst])) ----------------
template<int H>
__global__ void edgeA_kernel(const int* __restrict__ ei,
                             const float* __restrict__ als,
                             const float* __restrict__ ald,
                             float* __restrict__ p,
                             float* __restrict__ denom) {
    int i = blockIdx.x * blockDim.x + threadIdx.x;
    if (i >= E_TOT * H) return;
    int e = i / H, h = i % H;
    int s, d;
    if (e < E_EDGES) { s = ei[e]; d = ei[E_EDGES + e]; }
    else             { s = d = e - E_EDGES; }
    float v = als[s * H + h] + ald[d * H + h];
    v = (v > 0.f) ? v : SLOPE * v;
    float pe = expf(v);          // softmax is shift-invariant; logits are tiny
    p[i] = pe;
    atomicAdd(&denom[d * H + h], pe);
}

// ---------------- edge pass B: O[dst] += h[src] * alpha ----------------
template<int H, int F>          // F = feats per head; FO = H*F total
__global__ void edgeB_kernel(const int* __restrict__ ei,
                             const float* __restrict__ Hfeat,
                             const float* __restrict__ p,
                             const float* __restrict__ denom,
                             float* __restrict__ O) {
    constexpr int FO = H * F;
    constexpr int T  = FO / 4;   // threads per edge, each handles float4
    int i = blockIdx.x * blockDim.x + threadIdx.x;
    if (i >= E_TOT * T) return;
    int e = i / T, t = i % T;
    int s, d;
    if (e < E_EDGES) { s = ei[e]; d = ei[E_EDGES + e]; }
    else             { s = d = e - E_EDGES; }
    int h = (t * 4) / F;
    float alpha = p[e * H + h] / denom[d * H + h];
    float4 hv = reinterpret_cast<const float4*>(Hfeat + s * FO)[t];
    float4 v  = make_float4(hv.x * alpha, hv.y * alpha, hv.z * alpha, hv.w * alpha);
    atomicAdd(reinterpret_cast<float4*>(O + d * FO) + t, v);   // sm_90+ vec red
}

// ---------------- final: log_softmax(O + b3) over 64 classes ----------------
__global__ void final_kernel(const float* __restrict__ O,
                             const float* __restrict__ b3,
                             float* __restrict__ out) {
    int warp = (blockIdx.x * blockDim.x + threadIdx.x) >> 5;
    int lane = threadIdx.x & 31;
    if (warp >= N_NODES) return;
    const float* row = O + warp * 64;
    float v0 = row[lane]      + b3[lane];
    float v1 = row[32 + lane] + b3[32 + lane];
    float mx = fmaxf(v0, v1);
#pragma unroll
    for (int o = 16; o > 0; o >>= 1) mx = fmaxf(mx, __shfl_xor_sync(0xffffffffu, mx, o));
    float se = expf(v0 - mx) + expf(v1 - mx);
#pragma unroll
    for (int o = 16; o > 0; o >>= 1) se += __shfl_xor_sync(0xffffffffu, se, o);
    float lse = mx + logf(se);
    out[warp * 64 + lane]      = v0 - lse;
    out[warp * 64 + 32 + lane] = v1 - lse;
}

// ---------------- launcher ----------------
extern "C" void kernel_launch(void* const* d_in, const int* in_sizes, int n_in,
                              void* d_out, int out_size) {
    const float* x   = (const float*)d_in[0];
    const int*   ei  = (const int*)  d_in[1];
    const float* w1  = (const float*)d_in[2];
    const float* as1 = (const float*)d_in[3];
    const float* ad1 = (const float*)d_in[4];
    const float* b1  = (const float*)d_in[5];
    const float* w2  = (const float*)d_in[6];
    const float* as2 = (const float*)d_in[7];
    const float* ad2 = (const float*)d_in[8];
    const float* b2  = (const float*)d_in[9];
    const float* w3  = (const float*)d_in[10];
    const float* as3 = (const float*)d_in[11];
    const float* ad3 = (const float*)d_in[12];
    const float* b3  = (const float*)d_in[13];
    float* out = (float*)d_out;

    float *hbuf, *obuf, *als, *ald, *den, *pbuf;
    cudaGetSymbolAddress((void**)&hbuf, g_h);
    cudaGetSymbolAddress((void**)&obuf, g_o);
    cudaGetSymbolAddress((void**)&als,  g_als);
    cudaGetSymbolAddress((void**)&ald,  g_ald);
    cudaGetSymbolAddress((void**)&den,  g_denom);
    cudaGetSymbolAddress((void**)&pbuf, g_p);

    const int gemmGrid = (N_NODES + 15) / 16;
    auto cdiv = [](long long a, long long b) { return (int)((a + b - 1) / b); };

    // ---- layer 1: x @ w1, heads=4, hid=32 ----
    zero_kernel<<<cdiv(N_NODES * 128, 256), 256>>>(obuf, N_NODES * 128);
    gemm_kernel<128><<<gemmGrid, 128>>>(x, w1, nullptr, hbuf);
    coef_kernel<4, 32><<<cdiv(N_NODES * 4, 256), 256>>>(hbuf, as1, ad1, als, ald, den);
    edgeA_kernel<4><<<cdiv((long long)E_TOT * 4, 256), 256>>>(ei, als, ald, pbuf, den);
    edgeB_kernel<4, 32><<<cdiv((long long)E_TOT * 32, 256), 256>>>(ei, hbuf, pbuf, den, obuf);

    // ---- layer 2: relu(o + b1) @ w2 ----
    gemm_kernel<128><<<gemmGrid, 128>>>(obuf, w2, b1, hbuf);
    zero_kernel<<<cdiv(N_NODES * 128, 256), 256>>>(obuf, N_NODES * 128);
    coef_kernel<4, 32><<<cdiv(N_NODES * 4, 256), 256>>>(hbuf, as2, ad2, als, ald, den);
    edgeA_kernel<4><<<cdiv((long long)E_TOT * 4, 256), 256>>>(ei, als, ald, pbuf, den);
    edgeB_kernel<4, 32><<<cdiv((long long)E_TOT * 32, 256), 256>>>(ei, hbuf, pbuf, den, obuf);

    // ---- layer 3: relu(o + b2) @ w3, single head, 64 classes ----
    gemm_kernel<64><<<gemmGrid, 64>>>(obuf, w3, b2, hbuf);
    zero_kernel<<<cdiv(N_NODES * 64, 256), 256>>>(obuf, N_NODES * 64);
    coef_kernel<1, 64><<<cdiv(N_NODES, 256), 256>>>(hbuf, as3, ad3, als, ald, den);
    edgeA_kernel<1><<<cdiv((long long)E_TOT, 256), 256>>>(ei, als, ald, pbuf, den);
    edgeB_kernel<1, 64><<<cdiv((long long)E_TOT * 16, 256), 256>>>(ei, hbuf, pbuf, den, obuf);

    // ---- log_softmax ----
    final_kernel<<<cdiv((long long)N_NODES * 32, 256), 256>>>(obuf, b3, out);
}

// round 2
// speedup vs baseline: 1.2764x; 1.2764x over previous
#include <cuda_runtime.h>
#include <math.h>

#define N_NODES 50000
#define E_EDGES 800000
#define E_TOT   (E_EDGES + N_NODES)   // 850000 with self loops
#define F_IN    128
#define SLOPE   0.2f

// ---------------- scratch (static __device__ — no allocation) ----------------
__device__ float g_h[N_NODES * 128];        // transformed features
__device__ float g_o[N_NODES * 128];        // aggregated output
__device__ float g_als[N_NODES * 4];
__device__ float g_ald[N_NODES * 4];
__device__ float g_p[E_TOT * 4];            // exp(e) per edge (CSR order)
__device__ int   g_cnt[N_NODES];
__device__ int   g_off[N_NODES + 1];
__device__ int   g_cur[N_NODES];
__device__ int   g_csrc[E_TOT];

// ---------------- CSR build ----------------
__global__ void zero_int_kernel(int* p, int n) {
    int i = blockIdx.x * blockDim.x + threadIdx.x;
    if (i < n) p[i] = 0;
}

__global__ void hist_kernel(const int* __restrict__ ei, int* __restrict__ cnt) {
    int e = blockIdx.x * blockDim.x + threadIdx.x;
    if (e >= E_TOT) return;
    int d = (e < E_EDGES) ? ei[E_EDGES + e] : (e - E_EDGES);
    atomicAdd(&cnt[d], 1);
}

__global__ void scan_kernel(const int* __restrict__ cnt,
                            int* __restrict__ offsets,
                            int* __restrict__ cursor) {
    __shared__ int part[1024];
    const int T = 1024;
    const int C = (N_NODES + T - 1) / T;   // 49
    int t = threadIdx.x;
    int lo = t * C;
    int hi = lo + C; if (hi > N_NODES) hi = N_NODES;
    int s = 0;
    for (int i = lo; i < hi; i++) s += cnt[i];
    part[t] = s;
    __syncthreads();
    for (int off = 1; off < T; off <<= 1) {
        int v = (t >= off) ? part[t - off] : 0;
        __syncthreads();
        part[t] += v;
        __syncthreads();
    }
    int run = (t > 0) ? part[t - 1] : 0;   // exclusive base
    for (int i = lo; i < hi; i++) {
        offsets[i] = run;
        cursor[i]  = run;
        run += cnt[i];
    }
    if (t == 0) offsets[N_NODES] = E_TOT;
}

__global__ void scatter_kernel(const int* __restrict__ ei,
                               int* __restrict__ cursor,
                               int* __restrict__ csr_src) {
    int e = blockIdx.x * blockDim.x + threadIdx.x;
    if (e >= E_TOT) return;
    int s, d;
    if (e < E_EDGES) { s = ei[e]; d = ei[E_EDGES + e]; }
    else             { s = d = e - E_EDGES; }
    int pos = atomicAdd(&cursor[d], 1);
    csr_src[pos] = s;
}

// ---------------- GEMM: H = act(X + bias) @ W ----------------
// X: [N, F_IN] fp32 row-major, W: [F_IN, MO] row-major.
// bias != null -> relu(x + bias) applied to input (fused previous epilogue).
template<int MO>
__global__ void gemm_kernel(const float* __restrict__ X,
                            const float* __restrict__ W,
                            const float* __restrict__ bias,
                            float* __restrict__ Hout) {
    constexpr int GROUPS = 256 / MO;
    constexpr int ROWS = 16;
    constexpr int RT = ROWS * GROUPS;      // rows per block
    __shared__ float4 xs[RT][F_IN / 4];
    const int row0 = blockIdx.x * RT;
    const int t = threadIdx.x;

    for (int i = t; i < RT * (F_IN / 4); i += 256) {
        int r  = i / (F_IN / 4);
        int k4 = i % (F_IN / 4);
        int n  = row0 + r;
        float4 v = make_float4(0.f, 0.f, 0.f, 0.f);
        if (n < N_NODES) {
            v = reinterpret_cast<const float4*>(X)[n * (F_IN / 4) + k4];
            if (bias) {
                float4 b = reinterpret_cast<const float4*>(bias)[k4];
                v.x = fmaxf(v.x + b.x, 0.f);
                v.y = fmaxf(v.y + b.y, 0.f);
                v.z = fmaxf(v.z + b.z, 0.f);
                v.w = fmaxf(v.w + b.w, 0.f);
            }
        }
        xs[r][k4] = v;
    }
    __syncthreads();

    const int col = t % MO;
    const int g   = t / MO;
    float acc[ROWS];
#pragma unroll
    for (int r = 0; r < ROWS; r++) acc[r] = 0.f;

    for (int k4 = 0; k4 < F_IN / 4; k4++) {
        float w0 = W[(k4 * 4 + 0) * MO + col];
        float w1 = W[(k4 * 4 + 1) * MO + col];
        float w2 = W[(k4 * 4 + 2) * MO + col];
        float w3 = W[(k4 * 4 + 3) * MO + col];
#pragma unroll
        for (int r = 0; r < ROWS; r++) {
            float4 xv = xs[g * ROWS + r][k4];
            acc[r] = fmaf(xv.x, w0, acc[r]);
            acc[r] = fmaf(xv.y, w1, acc[r]);
            acc[r] = fmaf(xv.z, w2, acc[r]);
            acc[r] = fmaf(xv.w, w3, acc[r]);
        }
    }

#pragma unroll
    for (int r = 0; r < ROWS; r++) {
        int n = row0 + g * ROWS + r;
        if (n < N_NODES) Hout[n * MO + col] = acc[r];
    }
}

// ---------------- attention coefficients ----------------
template<int H, int F>
__global__ void coef_kernel(const float* __restrict__ Hfeat,
                            const float* __restrict__ a_src,
                            const float* __restrict__ a_dst,
                            float* __restrict__ als, float* __restrict__ ald) {
    int i = blockIdx.x * blockDim.x + threadIdx.x;   // n*H + h
    if (i >= N_NODES * H) return;
    int n = i / H, h = i % H;
    const float* hp = Hfeat + n * (H * F) + h * F;
    const float* as = a_src + h * F;
    const float* ad = a_dst + h * F;
    float s = 0.f, d = 0.f;
#pragma unroll 8
    for (int f = 0; f < F; f++) {
        float v = hp[f];
        s = fmaf(v, as[f], s);
        d = fmaf(v, ad[f], d);
    }
    als[i] = s;
    ald[i] = d;
}

// ---------------- fused attention softmax + gather (H=4, F=32) ----------------
__global__ void gather4_kernel(const int* __restrict__ offsets,
                               const int* __restrict__ csr_src,
                               const float* __restrict__ als,
                               const float* __restrict__ ald,
                               const float* __restrict__ Hfeat,
                               float4* __restrict__ p_csr,
                               float* __restrict__ O) {
    int warp = (blockIdx.x * blockDim.x + threadIdx.x) >> 5;
    int lane = threadIdx.x & 31;
    if (warp >= N_NODES) return;
    const int d = warp;
    const int start = offsets[d], end = offsets[d + 1];

    float4 aldv = reinterpret_cast<const float4*>(ald)[d];
    float dx = 0.f, dy = 0.f, dz = 0.f, dw = 0.f;
    for (int j = start + lane; j < end; j += 32) {
        int s = csr_src[j];
        float4 a = reinterpret_cast<const float4*>(als)[s];
        float ex = a.x + aldv.x; ex = (ex > 0.f) ? ex : SLOPE * ex; ex = __expf(ex);
        float ey = a.y + aldv.y; ey = (ey > 0.f) ? ey : SLOPE * ey; ey = __expf(ey);
        float ez = a.z + aldv.z; ez = (ez > 0.f) ? ez : SLOPE * ez; ez = __expf(ez);
        float ew = a.w + aldv.w; ew = (ew > 0.f) ? ew : SLOPE * ew; ew = __expf(ew);
        p_csr[j] = make_float4(ex, ey, ez, ew);
        dx += ex; dy += ey; dz += ez; dw += ew;
    }
#pragma unroll
    for (int o = 16; o > 0; o >>= 1) {
        dx += __shfl_xor_sync(0xffffffffu, dx, o);
        dy += __shfl_xor_sync(0xffffffffu, dy, o);
        dz += __shfl_xor_sync(0xffffffffu, dz, o);
        dw += __shfl_xor_sync(0xffffffffu, dw, o);
    }
    const int h = lane >> 3;                       // head for this lane's float4
    float den = (h == 0) ? dx : (h == 1) ? dy : (h == 2) ? dz : dw;
    float invd = __fdividef(1.f, den);

    const float* ps = reinterpret_cast<const float*>(p_csr);
    float4 acc = make_float4(0.f, 0.f, 0.f, 0.f);
    for (int j = start; j < end; j++) {
        int s = csr_src[j];                        // broadcast
        float alpha = ps[j * 4 + h] * invd;
        float4 hv = reinterpret_cast<const float4*>(Hfeat)[s * 32 + lane];
        acc.x = fmaf(hv.x, alpha, acc.x);
        acc.y = fmaf(hv.y, alpha, acc.y);
        acc.z = fmaf(hv.z, alpha, acc.z);
        acc.w = fmaf(hv.w, alpha, acc.w);
    }
    reinterpret_cast<float4*>(O)[d * 32 + lane] = acc;
}

// ---------------- fused attention softmax + gather (H=1, F=64) ----------------
__global__ void gather1_kernel(const int* __restrict__ offsets,
                               const int* __restrict__ csr_src,
                               const float* __restrict__ als,
                               const float* __restrict__ ald,
                               const float* __restrict__ Hfeat,
                               float* __restrict__ p_csr,
                               float* __restrict__ O) {
    int warp = (blockIdx.x * blockDim.x + threadIdx.x) >> 5;
    int lane = threadIdx.x & 31;
    if (warp >= N_NODES) return;
    const int d = warp;
    const int start = offsets[d], end = offsets[d + 1];

    float aldd = ald[d];
    float den = 0.f;
    for (int j = start + lane; j < end; j += 32) {
        int s = csr_src[j];
        float e = als[s] + aldd;
        e = (e > 0.f) ? e : SLOPE * e;
        e = __expf(e);
        p_csr[j] = e;
        den += e;
    }
#pragma unroll
    for (int o = 16; o > 0; o >>= 1) den += __shfl_xor_sync(0xffffffffu, den, o);
    float invd = __fdividef(1.f, den);

    float2 acc = make_float2(0.f, 0.f);
    for (int j = start; j < end; j++) {
        int s = csr_src[j];
        float alpha = p_csr[j] * invd;
        float2 hv = reinterpret_cast<const float2*>(Hfeat)[s * 32 + lane];
        acc.x = fmaf(hv.x, alpha, acc.x);
        acc.y = fmaf(hv.y, alpha, acc.y);
    }
    reinterpret_cast<float2*>(O)[d * 32 + lane] = acc;
}

// ---------------- final: log_softmax(O + b3) over 64 classes ----------------
__global__ void final_kernel(const float* __restrict__ O,
                             const float* __restrict__ b3,
                             float* __restrict__ out) {
    int warp = (blockIdx.x * blockDim.x + threadIdx.x) >> 5;
    int lane = threadIdx.x & 31;
    if (warp >= N_NODES) return;
    const float* row = O + warp * 64;
    float v0 = row[lane]      + b3[lane];
    float v1 = row[32 + lane] + b3[32 + lane];
    float mx = fmaxf(v0, v1);
#pragma unroll
    for (int o = 16; o > 0; o >>= 1) mx = fmaxf(mx, __shfl_xor_sync(0xffffffffu, mx, o));
    float se = expf(v0 - mx) + expf(v1 - mx);
#pragma unroll
    for (int o = 16; o > 0; o >>= 1) se += __shfl_xor_sync(0xffffffffu, se, o);
    float lse = mx + logf(se);
    out[warp * 64 + lane]      = v0 - lse;
    out[warp * 64 + 32 + lane] = v1 - lse;
}

// ---------------- launcher ----------------
extern "C" void kernel_launch(void* const* d_in, const int* in_sizes, int n_in,
                              void* d_out, int out_size) {
    const float* x   = (const float*)d_in[0];
    const int*   ei  = (const int*)  d_in[1];
    const float* w1  = (const float*)d_in[2];
    const float* as1 = (const float*)d_in[3];
    const float* ad1 = (const float*)d_in[4];
    const float* b1  = (const float*)d_in[5];
    const float* w2  = (const float*)d_in[6];
    const float* as2 = (const float*)d_in[7];
    const float* ad2 = (const float*)d_in[8];
    const float* b2  = (const float*)d_in[9];
    const float* w3  = (const float*)d_in[10];
    const float* as3 = (const float*)d_in[11];
    const float* ad3 = (const float*)d_in[12];
    const float* b3  = (const float*)d_in[13];
    float* out = (float*)d_out;

    float *hbuf, *obuf, *als, *ald, *pbuf;
    int *cnt, *off, *cur, *csrc;
    cudaGetSymbolAddress((void**)&hbuf, g_h);
    cudaGetSymbolAddress((void**)&obuf, g_o);
    cudaGetSymbolAddress((void**)&als,  g_als);
    cudaGetSymbolAddress((void**)&ald,  g_ald);
    cudaGetSymbolAddress((void**)&pbuf, g_p);
    cudaGetSymbolAddress((void**)&cnt,  g_cnt);
    cudaGetSymbolAddress((void**)&off,  g_off);
    cudaGetSymbolAddress((void**)&cur,  g_cur);
    cudaGetSymbolAddress((void**)&csrc, g_csrc);

    auto cdiv = [](long long a, long long b) { return (int)((a + b - 1) / b); };

    // ---- CSR build (by destination) ----
    zero_int_kernel<<<cdiv(N_NODES, 256), 256>>>(cnt, N_NODES);
    hist_kernel<<<cdiv(E_TOT, 256), 256>>>(ei, cnt);
    scan_kernel<<<1, 1024>>>(cnt, off, cur);
    scatter_kernel<<<cdiv(E_TOT, 256), 256>>>(ei, cur, csrc);

    const int gatherGrid = cdiv((long long)N_NODES * 32, 256);

    // ---- layer 1 ----
    gemm_kernel<128><<<cdiv(N_NODES, 32), 256>>>(x, w1, nullptr, hbuf);
    coef_kernel<4, 32><<<cdiv(N_NODES * 4, 256), 256>>>(hbuf, as1, ad1, als, ald);
    gather4_kernel<<<gatherGrid, 256>>>(off, csrc, als, ald, hbuf,
                                        (float4*)pbuf, obuf);

    // ---- layer 2 ----
    gemm_kernel<128><<<cdiv(N_NODES, 32), 256>>>(obuf, w2, b1, hbuf);
    coef_kernel<4, 32><<<cdiv(N_NODES * 4, 256), 256>>>(hbuf, as2, ad2, als, ald);
    gather4_kernel<<<gatherGrid, 256>>>(off, csrc, als, ald, hbuf,
                                        (float4*)pbuf, obuf);

    // ---- layer 3 ----
    gemm_kernel<64><<<cdiv(N_NODES, 64), 256>>>(obuf, w3, b2, hbuf);
    coef_kernel<1, 64><<<cdiv(N_NODES, 256), 256>>>(hbuf, as3, ad3, als, ald);
    gather1_kernel<<<gatherGrid, 256>>>(off, csrc, als, ald, hbuf, pbuf, obuf);

    // ---- log_softmax ----
    final_kernel<<<gatherGrid, 256>>>(obuf, b3, out);
}